// round 2
// baseline (speedup 1.0000x reference)
#include <cuda_runtime.h>
#include <math.h>

#define N_ATOMS 10000
#define N_EDGES 320000
#define NCH 16
// K = [128, 96, 64, 32], n_max = [8,6,4,2]
// A/B feature vector layout (960): l0 [0,128) | l1 [128,416) m-major | l2 [416,736) | l3 [736,960)
#define FV 960

// ---------------- scratch (static device memory; no allocations) -------------
__device__ float g_geo[N_EDGES * 24];      // per edge: R[8], Y1..Y15 (lm=1..15), species(sender) as bits
__device__ int   g_deg[N_ATOMS];
__device__ int   g_fill[N_ATOMS];
__device__ int   g_off[N_ATOMS + 1];
__device__ int   g_csr[N_EDGES];
__device__ float g_Aemb[(size_t)N_ATOMS * FV];
__device__ float g_eatom[N_ATOMS];

// ---------------- kernel 0: zero counters ------------------------------------
__global__ void k_zero() {
    int i = blockIdx.x * blockDim.x + threadIdx.x;
    if (i < N_ATOMS) { g_deg[i] = 0; g_fill[i] = 0; }
}

// ---------------- kernel 1: per-edge geometry + degree count -----------------
__global__ void k_geom(const float* __restrict__ pos, const int* __restrict__ species,
                       const int* __restrict__ snd, const int* __restrict__ rcv) {
    int e = blockIdx.x * blockDim.x + threadIdx.x;
    if (e >= N_EDGES) return;
    int si = snd[e], ri = rcv[e];
    float dx = pos[ri * 3 + 0] - pos[si * 3 + 0];
    float dy = pos[ri * 3 + 1] - pos[si * 3 + 1];
    float dz = pos[ri * 3 + 2] - pos[si * 3 + 2];
    float r = sqrtf(dx * dx + dy * dy + dz * dz + 1e-12f);
    float inv = 1.0f / r;
    float x = dx * inv, y = dy * inv, z = dz * inv;
    float fc = (r < 5.0f) ? 0.5f * (cosf(3.14159265358979f * r * 0.2f) + 1.0f) : 0.0f;

    float* g = g_geo + (size_t)e * 24;
    #pragma unroll
    for (int b = 0; b < 8; b++) {
        float mu = (5.0f / 7.0f) * (float)b;
        float d2 = r - mu;
        g[b] = expf(-d2 * d2) * fc;
    }
    const float s3  = 1.7320508075688772f;
    const float c33 = 0.7905694150420949f;  // sqrt(10)/4
    const float c31 = 0.6123724356957945f;  // sqrt(6)/4
    const float s15 = 3.872983346207417f;
    // Y1 (lm 1..3)
    g[8]  = x; g[9] = y; g[10] = z;
    // Y2 (lm 4..8)
    g[11] = s3 * x * y;
    g[12] = s3 * y * z;
    g[13] = 0.5f * (3.0f * z * z - 1.0f);
    g[14] = s3 * x * z;
    g[15] = 0.5f * s3 * (x * x - y * y);
    // Y3 (lm 9..15)
    g[16] = c33 * y * (3.0f * x * x - y * y);
    g[17] = s15 * x * y * z;
    g[18] = c31 * y * (5.0f * z * z - 1.0f);
    g[19] = 0.5f * z * (5.0f * z * z - 3.0f);
    g[20] = c31 * x * (5.0f * z * z - 1.0f);
    g[21] = 0.5f * s15 * (x * x - y * y) * z;
    g[22] = c33 * x * (x * x - 3.0f * y * y);
    g[23] = __int_as_float(species[si]);
    atomicAdd(&g_deg[ri], 1);
}

// ---------------- kernel 2: exclusive scan of degrees ------------------------
__global__ void k_scan() {
    __shared__ int sh[1024];
    int t = threadIdx.x;
    const int CH = 10;                       // 1024*10 >= 10000
    int base = t * CH;
    int loc[CH];
    int s = 0;
    #pragma unroll
    for (int j = 0; j < CH; j++) {
        int idx = base + j;
        int v = (idx < N_ATOMS) ? g_deg[idx] : 0;
        loc[j] = v; s += v;
    }
    sh[t] = s;
    __syncthreads();
    for (int o = 1; o < 1024; o <<= 1) {
        int v = (t >= o) ? sh[t - o] : 0;
        __syncthreads();
        sh[t] += v;
        __syncthreads();
    }
    int ex = sh[t] - s;                      // exclusive prefix for this chunk
    #pragma unroll
    for (int j = 0; j < CH; j++) {
        int idx = base + j;
        if (idx < N_ATOMS) { g_off[idx] = ex; ex += loc[j]; }
    }
    if (t == 1023) g_off[N_ATOMS] = sh[1023];
}

// ---------------- kernel 3: CSR fill ------------------------------------------
__global__ void k_fill(const int* __restrict__ rcv) {
    int e = blockIdx.x * blockDim.x + threadIdx.x;
    if (e >= N_EDGES) return;
    int r = rcv[e];
    int p = g_off[r] + atomicAdd(&g_fill[r], 1);
    g_csr[p] = e;
}

// ---------------- kernel 4: phase A gather (one block per atom) --------------
// thread t = b*16 + lm  (128 threads). Accumulates T[s][b][lm] in registers,
// then contracts with emb and Wr into A_emb[i].
__global__ void __launch_bounds__(128) k_phaseA(
    const float* __restrict__ emb,
    const float* __restrict__ Wr0, const float* __restrict__ Wr1,
    const float* __restrict__ Wr2, const float* __restrict__ Wr3,
    const int* __restrict__ species) {
    __shared__ float wr[2560];
    __shared__ float em[64];
    __shared__ float T[512];
    __shared__ float E1[2048];
    __shared__ float sg[16 * 24];
    __shared__ int es[16];

    int t = threadIdx.x;
    int i = blockIdx.x;

    for (int j = t; j < 1024; j += 128) wr[j] = Wr0[j];
    for (int j = t; j < 768;  j += 128) wr[1024 + j] = Wr1[j];
    for (int j = t; j < 512;  j += 128) wr[1792 + j] = Wr2[j];
    for (int j = t; j < 256;  j += 128) wr[2304 + j] = Wr3[j];
    if (t < 64) em[t] = emb[t];

    int b = t >> 4, lm = t & 15;
    float a0 = 0.f, a1 = 0.f, a2 = 0.f, a3 = 0.f;
    int start = g_off[i];
    int deg = g_off[i + 1] - start;
    __syncthreads();

    for (int c0 = 0; c0 < deg; c0 += 16) {
        int nn = min(16, deg - c0);
        if (t < nn) es[t] = g_csr[start + c0 + t];
        __syncthreads();
        for (int j = t; j < nn * 24; j += 128) {
            int ec = j / 24, w = j - ec * 24;
            sg[ec * 24 + w] = g_geo[(size_t)es[ec] * 24 + w];
        }
        __syncthreads();
        for (int ec = 0; ec < nn; ec++) {
            float R  = sg[ec * 24 + b];
            float Yv = (lm == 0) ? 1.0f : sg[ec * 24 + 7 + lm];
            int sp = __float_as_int(sg[ec * 24 + 23]);
            float v = R * Yv;
            if      (sp == 0) a0 += v;
            else if (sp == 1) a1 += v;
            else if (sp == 2) a2 += v;
            else              a3 += v;
        }
        __syncthreads();
    }
    T[t]       = a0;
    T[128 + t] = a1;
    T[256 + t] = a2;
    T[384 + t] = a3;
    __syncthreads();

    // E1[c][b][lm] = sum_s emb[s,c] * T[s][b][lm]
    for (int j = t; j < 2048; j += 128) {
        int c = j >> 7, rest = j & 127;
        E1[j] = em[0 * 16 + c] * T[0 * 128 + rest]
              + em[1 * 16 + c] * T[1 * 128 + rest]
              + em[2 * 16 + c] * T[2 * 128 + rest]
              + em[3 * 16 + c] * T[3 * 128 + rest];
    }
    __syncthreads();

    int spi = species[i];
    float* out = g_Aemb + (size_t)i * FV;
    for (int kp = t; kp < FV; kp += 128) {
        int k, Kl, nmax, lmb, woff;
        if (kp < 128)      { k = kp;                         Kl = 128; nmax = 8; lmb = 0; woff = 0;    }
        else if (kp < 416) { int u = kp - 128; int m = u / 96; k = u - 96 * m; Kl = 96; nmax = 6; lmb = 1 + m; woff = 1024; }
        else if (kp < 736) { int u = kp - 416; int m = u >> 6; k = u & 63;     Kl = 64; nmax = 4; lmb = 4 + m; woff = 1792; }
        else               { int u = kp - 736; int m = u >> 5; k = u & 31;     Kl = 32; nmax = 2; lmb = 9 + m; woff = 2304; }
        int c = k / nmax;
        float v = 0.f;
        #pragma unroll
        for (int bb = 0; bb < 8; bb++)
            v += wr[woff + bb * Kl + k] * E1[c * 128 + bb * 16 + lmb];
        out[kp] = 0.1f * em[spi * 16 + c] * v;
    }
}

// ---------------- kernel 5: phase B gather + invariants + MLP ----------------
__global__ void __launch_bounds__(256) k_phaseB(
    const float* __restrict__ Vr0, const float* __restrict__ Vr1,
    const float* __restrict__ Vr2, const float* __restrict__ Vr3,
    const float* __restrict__ N1, const float* __restrict__ N2,
    const float* __restrict__ N3,
    const float* __restrict__ W1, const float* __restrict__ W2,
    const float* __restrict__ w_out, const float* __restrict__ comp,
    const int* __restrict__ snd, const int* __restrict__ species) {
    __shared__ float vr[2560];
    __shared__ int   se[32];
    __shared__ int   ee[32];
    __shared__ float Re[32 * 8];
    __shared__ float Bsh[FV];
    __shared__ float invsh[192];
    __shared__ float f2sh[128];
    __shared__ float h1sh[128];
    __shared__ float red[4];

    int t = threadIdx.x;
    int i = blockIdx.x;

    for (int j = t; j < 1024; j += 256) vr[j] = Vr0[j];
    for (int j = t; j < 768;  j += 256) vr[1024 + j] = Vr1[j];
    for (int j = t; j < 512;  j += 256) vr[1792 + j] = Vr2[j];
    for (int j = t; j < 256;  j += 256) vr[2304 + j] = Vr3[j];

    // per-thread column assignments: kp = t + 256*j, j = 0..3
    int voff[4], kst[4];
    bool valid[4];
    #pragma unroll
    for (int j = 0; j < 4; j++) {
        int kp = t + 256 * j;
        valid[j] = (kp < FV);
        int k = 0, Kl = 128, base = 0;
        if (kp < 128)      { k = kp;                              Kl = 128; base = 0;    }
        else if (kp < 416) { int u = kp - 128; k = u % 96;        Kl = 96;  base = 1024; }
        else if (kp < 736) { int u = kp - 416; k = u & 63;        Kl = 64;  base = 1792; }
        else if (kp < FV)  { int u = kp - 736; k = u & 31;        Kl = 32;  base = 2304; }
        voff[j] = base + k;
        kst[j]  = Kl;
    }
    float acc0 = 0.f, acc1 = 0.f, acc2 = 0.f, acc3 = 0.f;

    int start = g_off[i];
    int deg = g_off[i + 1] - start;
    __syncthreads();

    for (int c0 = 0; c0 < deg; c0 += 32) {
        int nn = min(32, deg - c0);
        if (t < nn) {
            int e = g_csr[start + c0 + t];
            ee[t] = e;
            se[t] = snd[e];
        }
        __syncthreads();
        for (int j = t; j < nn * 8; j += 256) {
            int ec = j >> 3, bb = j & 7;
            Re[ec * 8 + bb] = g_geo[(size_t)ee[ec] * 24 + bb];
        }
        __syncthreads();
        for (int ec = 0; ec < nn; ec++) {
            const float* arow = g_Aemb + (size_t)se[ec] * FV;
            const float* rp = &Re[ec * 8];
            float r0 = rp[0], r1 = rp[1], r2 = rp[2], r3 = rp[3];
            float r4 = rp[4], r5 = rp[5], r6 = rp[6], r7 = rp[7];
            #pragma unroll
            for (int j = 0; j < 4; j++) {
                if (!valid[j]) continue;
                const float* vp = &vr[voff[j]];
                int st = kst[j];
                float vl = r0 * vp[0]
                         + r1 * vp[st]
                         + r2 * vp[2 * st]
                         + r3 * vp[3 * st]
                         + r4 * vp[4 * st]
                         + r5 * vp[5 * st]
                         + r6 * vp[6 * st]
                         + r7 * vp[7 * st];
                float a = arow[t + 256 * j];
                if      (j == 0) acc0 += a * vl;
                else if (j == 1) acc1 += a * vl;
                else if (j == 2) acc2 += a * vl;
                else             acc3 += a * vl;
            }
        }
        __syncthreads();
    }

    Bsh[t]       = 0.1f * acc0;
    Bsh[t + 256] = 0.1f * acc1;
    Bsh[t + 512] = 0.1f * acc2;
    if (t < 192) Bsh[t + 768] = 0.1f * acc3;
    __syncthreads();

    // invariants: 192 of them (96 for l1, 64 for l2, 32 for l3)
    if (t < 192) {
        int off, Kl, cnt, k;
        float norm;
        if (t < 96)       { off = 128; Kl = 96; cnt = 3; k = t;       norm = 0.5773502691896258f; }
        else if (t < 160) { off = 416; Kl = 64; cnt = 5; k = t - 96;  norm = 0.4472135954999579f; }
        else              { off = 736; Kl = 32; cnt = 7; k = t - 160; norm = 0.3779644730092272f; }
        float s = 0.f;
        for (int m = 0; m < cnt; m++) { float v = Bsh[off + m * Kl + k]; s += v * v; }
        invsh[t] = s * norm;
    }
    __syncthreads();

    // f2 = B0 + inv @ N
    if (t < 128) {
        float s = Bsh[t];
        for (int j = 0; j < 96; j++) s += invsh[j]       * N1[j * 128 + t];
        for (int j = 0; j < 64; j++) s += invsh[96 + j]  * N2[j * 128 + t];
        for (int j = 0; j < 32; j++) s += invsh[160 + j] * N3[j * 128 + t];
        f2sh[t] = s;
    }
    __syncthreads();

    // h1 = silu(f2 @ W1)
    if (t < 128) {
        float s = 0.f;
        for (int k = 0; k < 128; k++) s += f2sh[k] * W1[k * 128 + t];
        h1sh[t] = s / (1.0f + expf(-s));
    }
    __syncthreads();

    // h2 = h1 @ W2 ;  partial = h2 * w_out ;  reduce
    if (t < 128) {
        float s = 0.f;
        for (int k = 0; k < 128; k++) s += h1sh[k] * W2[k * 128 + t];
        float p = s * w_out[t];
        #pragma unroll
        for (int o = 16; o > 0; o >>= 1) p += __shfl_down_sync(0xffffffffu, p, o);
        if ((t & 31) == 0) red[t >> 5] = p;
    }
    __syncthreads();
    if (t == 0) {
        float tot = red[0] + red[1] + red[2] + red[3];
        g_eatom[i] = tot + comp[species[i]];
    }
}

// ---------------- kernel 6: deterministic final reduction --------------------
__global__ void k_reduce(float* __restrict__ out) {
    __shared__ double sh[1024];
    int t = threadIdx.x;
    double s = 0.0;
    for (int i = t; i < N_ATOMS; i += 1024) s += (double)g_eatom[i];
    sh[t] = s;
    __syncthreads();
    for (int o = 512; o > 0; o >>= 1) {
        if (t < o) sh[t] += sh[t + o];
        __syncthreads();
    }
    if (t == 0) out[0] = (float)sh[0];
}

// ---------------- launch ------------------------------------------------------
// Inputs are resolved BY ELEMENT COUNT (robust to metadata ordering):
// every array has a unique size, or belongs to a pair whose relative order
// (first vs second occurrence) is the same in both the reference-signature
// ordering and the setup_inputs dict ordering.
extern "C" void kernel_launch(void* const* d_in, const int* in_sizes, int n_in,
                              void* d_out, int out_size) {
    const float *pos = 0, *emb = 0, *Wr0 = 0, *Wr1 = 0, *Wr2 = 0, *Wr3 = 0;
    const float *Vr0 = 0, *Vr1 = 0, *Vr2 = 0, *Vr3 = 0;
    const float *N1 = 0, *N2 = 0, *N3 = 0, *W1 = 0, *W2 = 0, *w_out = 0, *comp = 0;
    const int *species = 0, *snd = 0, *rcv = 0;

    for (int i = 0; i < n_in; i++) {
        int s = in_sizes[i];
        const void* p = d_in[i];
        switch (s) {
            case 30000:  pos = (const float*)p; break;
            case 64:     emb = (const float*)p; break;
            case 10000:  species = (const int*)p; break;
            case 320000: if (!snd) snd = (const int*)p; else rcv = (const int*)p; break;
            case 1024:   if (!Wr0) Wr0 = (const float*)p; else Vr0 = (const float*)p; break;
            case 768:    if (!Wr1) Wr1 = (const float*)p; else Vr1 = (const float*)p; break;
            case 512:    if (!Wr2) Wr2 = (const float*)p; else Vr2 = (const float*)p; break;
            case 256:    if (!Wr3) Wr3 = (const float*)p; else Vr3 = (const float*)p; break;
            case 12288:  if (!N1) N1 = (const float*)p; else N1 = (const float*)p; break; // M1 then N1
            case 8192:   N2 = (const float*)p; break;  // M2 then N2: keep LAST
            case 4096:   N3 = (const float*)p; break;  // M3 then N3: keep LAST
            case 16384:  if (!W1) W1 = (const float*)p; else W2 = (const float*)p; break;
            case 128:    w_out = (const float*)p; break;
            case 4:      comp = (const float*)p; break;
            default: break;
        }
    }
    // 12288 appears twice (M1 then N1); we want the SECOND (N1). The switch
    // above overwrote on each occurrence, so redo explicitly to keep last:
    {
        const float* last = 0;
        for (int i = 0; i < n_in; i++)
            if (in_sizes[i] == 12288) last = (const float*)d_in[i];
        N1 = last;
    }

    float* out = (float*)d_out;

    k_zero<<<(N_ATOMS + 255) / 256, 256>>>();
    k_geom<<<(N_EDGES + 255) / 256, 256>>>(pos, species, snd, rcv);
    k_scan<<<1, 1024>>>();
    k_fill<<<(N_EDGES + 255) / 256, 256>>>(rcv);
    k_phaseA<<<N_ATOMS, 128>>>(emb, Wr0, Wr1, Wr2, Wr3, species);
    k_phaseB<<<N_ATOMS, 256>>>(Vr0, Vr1, Vr2, Vr3, N1, N2, N3,
                               W1, W2, w_out, comp, snd, species);
    k_reduce<<<1, 1024>>>(out);
}

// round 4
// speedup vs baseline: 1.3920x; 1.3920x over previous
#include <cuda_runtime.h>
#include <math.h>

#define N_ATOMS 10000
#define N_EDGES 320000
// K = [128, 96, 64, 32], n_max = [8,6,4,2]
// A/B feature layout (960): l0 [0,128) | l1 [128,416) m-major | l2 [416,736) | l3 [736,960)
#define FV 960
#define FP 320   // fpre per atom: B0(128) + inv(192)

// ---------------- scratch (static device memory; no allocations) -------------
__device__ float g_geo[N_EDGES * 24];      // per edge: R[8], Y1..Y15, species(sender) bits
__device__ int   g_deg[N_ATOMS];
__device__ int   g_fill[N_ATOMS];
__device__ int   g_off[N_ATOMS + 1];
__device__ int   g_csr[N_EDGES];
__device__ float g_Aemb[(size_t)N_ATOMS * FV];
__device__ float g_fpre[(size_t)N_ATOMS * FP];
__device__ float g_eatom[N_ATOMS];

// ---------------- kernel 0: zero counters ------------------------------------
__global__ void k_zero() {
    int i = blockIdx.x * blockDim.x + threadIdx.x;
    if (i < N_ATOMS) { g_deg[i] = 0; g_fill[i] = 0; }
}

// ---------------- kernel 1: per-edge geometry + degree count -----------------
__global__ void k_geom(const float* __restrict__ pos, const int* __restrict__ species,
                       const int* __restrict__ snd, const int* __restrict__ rcv) {
    int e = blockIdx.x * blockDim.x + threadIdx.x;
    if (e >= N_EDGES) return;
    int si = snd[e], ri = rcv[e];
    float dx = pos[ri * 3 + 0] - pos[si * 3 + 0];
    float dy = pos[ri * 3 + 1] - pos[si * 3 + 1];
    float dz = pos[ri * 3 + 2] - pos[si * 3 + 2];
    float r = sqrtf(dx * dx + dy * dy + dz * dz + 1e-12f);
    float inv = 1.0f / r;
    float x = dx * inv, y = dy * inv, z = dz * inv;
    float fc = (r < 5.0f) ? 0.5f * (cosf(3.14159265358979f * r * 0.2f) + 1.0f) : 0.0f;

    float* g = g_geo + (size_t)e * 24;
    #pragma unroll
    for (int b = 0; b < 8; b++) {
        float mu = (5.0f / 7.0f) * (float)b;
        float d2 = r - mu;
        g[b] = expf(-d2 * d2) * fc;
    }
    const float s3  = 1.7320508075688772f;
    const float c33 = 0.7905694150420949f;
    const float c31 = 0.6123724356957945f;
    const float s15 = 3.872983346207417f;
    g[8]  = x; g[9] = y; g[10] = z;
    g[11] = s3 * x * y;
    g[12] = s3 * y * z;
    g[13] = 0.5f * (3.0f * z * z - 1.0f);
    g[14] = s3 * x * z;
    g[15] = 0.5f * s3 * (x * x - y * y);
    g[16] = c33 * y * (3.0f * x * x - y * y);
    g[17] = s15 * x * y * z;
    g[18] = c31 * y * (5.0f * z * z - 1.0f);
    g[19] = 0.5f * z * (5.0f * z * z - 3.0f);
    g[20] = c31 * x * (5.0f * z * z - 1.0f);
    g[21] = 0.5f * s15 * (x * x - y * y) * z;
    g[22] = c33 * x * (x * x - 3.0f * y * y);
    g[23] = __int_as_float(species[si]);
    atomicAdd(&g_deg[ri], 1);
}

// ---------------- kernel 2: exclusive scan of degrees ------------------------
__global__ void k_scan() {
    __shared__ int sh[1024];
    int t = threadIdx.x;
    const int CH = 10;
    int base = t * CH;
    int loc[CH];
    int s = 0;
    #pragma unroll
    for (int j = 0; j < CH; j++) {
        int idx = base + j;
        int v = (idx < N_ATOMS) ? g_deg[idx] : 0;
        loc[j] = v; s += v;
    }
    sh[t] = s;
    __syncthreads();
    for (int o = 1; o < 1024; o <<= 1) {
        int v = (t >= o) ? sh[t - o] : 0;
        __syncthreads();
        sh[t] += v;
        __syncthreads();
    }
    int ex = sh[t] - s;
    #pragma unroll
    for (int j = 0; j < CH; j++) {
        int idx = base + j;
        if (idx < N_ATOMS) { g_off[idx] = ex; ex += loc[j]; }
    }
    if (t == 1023) g_off[N_ATOMS] = sh[1023];
}

// ---------------- kernel 3: CSR fill ------------------------------------------
__global__ void k_fill(const int* __restrict__ rcv) {
    int e = blockIdx.x * blockDim.x + threadIdx.x;
    if (e >= N_EDGES) return;
    int r = rcv[e];
    int p = g_off[r] + atomicAdd(&g_fill[r], 1);
    g_csr[p] = e;
}

// ---------------- kernel 4: phase A gather (one block per atom) --------------
__global__ void __launch_bounds__(128) k_phaseA(
    const float* __restrict__ emb,
    const float* __restrict__ Wr0, const float* __restrict__ Wr1,
    const float* __restrict__ Wr2, const float* __restrict__ Wr3,
    const int* __restrict__ species) {
    __shared__ float wr[2560];
    __shared__ float em[64];
    __shared__ float T[512];
    __shared__ float E1[2048];
    __shared__ float sg[16 * 24];
    __shared__ int es[16];

    int t = threadIdx.x;
    int i = blockIdx.x;

    for (int j = t; j < 1024; j += 128) wr[j] = Wr0[j];
    for (int j = t; j < 768;  j += 128) wr[1024 + j] = Wr1[j];
    for (int j = t; j < 512;  j += 128) wr[1792 + j] = Wr2[j];
    for (int j = t; j < 256;  j += 128) wr[2304 + j] = Wr3[j];
    if (t < 64) em[t] = emb[t];

    int b = t >> 4, lm = t & 15;
    float a0 = 0.f, a1 = 0.f, a2 = 0.f, a3 = 0.f;
    int start = g_off[i];
    int deg = g_off[i + 1] - start;
    __syncthreads();

    for (int c0 = 0; c0 < deg; c0 += 16) {
        int nn = min(16, deg - c0);
        if (t < nn) es[t] = g_csr[start + c0 + t];
        __syncthreads();
        for (int j = t; j < nn * 24; j += 128) {
            int ec = j / 24, w = j - ec * 24;
            sg[ec * 24 + w] = g_geo[(size_t)es[ec] * 24 + w];
        }
        __syncthreads();
        for (int ec = 0; ec < nn; ec++) {
            float R  = sg[ec * 24 + b];
            float Yv = (lm == 0) ? 1.0f : sg[ec * 24 + 7 + lm];
            int sp = __float_as_int(sg[ec * 24 + 23]);
            float v = R * Yv;
            if      (sp == 0) a0 += v;
            else if (sp == 1) a1 += v;
            else if (sp == 2) a2 += v;
            else              a3 += v;
        }
        __syncthreads();
    }
    T[t]       = a0;
    T[128 + t] = a1;
    T[256 + t] = a2;
    T[384 + t] = a3;
    __syncthreads();

    for (int j = t; j < 2048; j += 128) {
        int c = j >> 7, rest = j & 127;
        E1[j] = em[0 * 16 + c] * T[0 * 128 + rest]
              + em[1 * 16 + c] * T[1 * 128 + rest]
              + em[2 * 16 + c] * T[2 * 128 + rest]
              + em[3 * 16 + c] * T[3 * 128 + rest];
    }
    __syncthreads();

    int spi = species[i];
    float* out = g_Aemb + (size_t)i * FV;
    for (int kp = t; kp < FV; kp += 128) {
        int k, Kl, nmax, lmb, woff;
        if (kp < 128)      { k = kp;                         Kl = 128; nmax = 8; lmb = 0; woff = 0;    }
        else if (kp < 416) { int u = kp - 128; int m = u / 96; k = u - 96 * m; Kl = 96; nmax = 6; lmb = 1 + m; woff = 1024; }
        else if (kp < 736) { int u = kp - 416; int m = u >> 6; k = u & 63;     Kl = 64; nmax = 4; lmb = 4 + m; woff = 1792; }
        else               { int u = kp - 736; int m = u >> 5; k = u & 31;     Kl = 32; nmax = 2; lmb = 9 + m; woff = 2304; }
        int c = k / nmax;
        float v = 0.f;
        #pragma unroll
        for (int bb = 0; bb < 8; bb++)
            v += wr[woff + bb * Kl + k] * E1[c * 128 + bb * 16 + lmb];
        out[kp] = 0.1f * em[spi * 16 + c] * v;
    }
}

// ---------------- kernel 5: phase B gather (one block per atom, 320 thr) -----
// One thread per DISTINCT Vl column k (320 of them). Vr coefficients live in
// registers; per edge: vl = <R, v> (8 FMA) then (2l+1) MACs gathering the
// sender's A_emb row. Emits fpre = [B0 (128) | inv (192)].
__global__ void __launch_bounds__(320) k_phaseB(
    const float* __restrict__ Vr0, const float* __restrict__ Vr1,
    const float* __restrict__ Vr2, const float* __restrict__ Vr3,
    const int* __restrict__ snd) {
    __shared__ int   se[32];
    __shared__ int   ee[32];
    __shared__ float Re[32 * 8];
    __shared__ float Bsh[FV];
    __shared__ float invsh[192];

    int t = threadIdx.x;
    int i = blockIdx.x;

    // column assignment (warp-homogeneous: w0-3 l0, w4-6 l1, w7-8 l2, w9 l3)
    int lvl, k, base;
    const float* Vp; int Kl;
    if (t < 128)      { lvl = 0; k = t;       base = k;       Vp = Vr0; Kl = 128; }
    else if (t < 224) { lvl = 1; k = t - 128; base = 128 + k; Vp = Vr1; Kl = 96;  }
    else if (t < 288) { lvl = 2; k = t - 224; base = 416 + k; Vp = Vr2; Kl = 64;  }
    else              { lvl = 3; k = t - 288; base = 736 + k; Vp = Vr3; Kl = 32;  }
    float v0 = Vp[0 * Kl + k], v1 = Vp[1 * Kl + k], v2 = Vp[2 * Kl + k], v3 = Vp[3 * Kl + k];
    float v4 = Vp[4 * Kl + k], v5 = Vp[5 * Kl + k], v6 = Vp[6 * Kl + k], v7 = Vp[7 * Kl + k];

    float a0 = 0.f, a1 = 0.f, a2 = 0.f, a3 = 0.f, a4 = 0.f, a5 = 0.f, a6 = 0.f;

    int start = g_off[i];
    int deg = g_off[i + 1] - start;

    for (int c0 = 0; c0 < deg; c0 += 32) {
        int nn = min(32, deg - c0);
        if (t < nn) {
            int e = g_csr[start + c0 + t];
            ee[t] = e;
            se[t] = snd[e];
        }
        __syncthreads();
        for (int j = t; j < nn * 8; j += 320) {
            int ec = j >> 3, bb = j & 7;
            Re[ec * 8 + bb] = g_geo[(size_t)ee[ec] * 24 + bb];
        }
        __syncthreads();

        if (lvl == 0) {
            #pragma unroll 2
            for (int ec = 0; ec < nn; ec++) {
                const float* ar = g_Aemb + (size_t)se[ec] * FV;
                const float* rp = &Re[ec * 8];
                float vl = rp[0]*v0 + rp[1]*v1 + rp[2]*v2 + rp[3]*v3
                         + rp[4]*v4 + rp[5]*v5 + rp[6]*v6 + rp[7]*v7;
                a0 += ar[base] * vl;
            }
        } else if (lvl == 1) {
            #pragma unroll 2
            for (int ec = 0; ec < nn; ec++) {
                const float* ar = g_Aemb + (size_t)se[ec] * FV;
                const float* rp = &Re[ec * 8];
                float vl = rp[0]*v0 + rp[1]*v1 + rp[2]*v2 + rp[3]*v3
                         + rp[4]*v4 + rp[5]*v5 + rp[6]*v6 + rp[7]*v7;
                a0 += ar[base]       * vl;
                a1 += ar[base + 96]  * vl;
                a2 += ar[base + 192] * vl;
            }
        } else if (lvl == 2) {
            #pragma unroll 2
            for (int ec = 0; ec < nn; ec++) {
                const float* ar = g_Aemb + (size_t)se[ec] * FV;
                const float* rp = &Re[ec * 8];
                float vl = rp[0]*v0 + rp[1]*v1 + rp[2]*v2 + rp[3]*v3
                         + rp[4]*v4 + rp[5]*v5 + rp[6]*v6 + rp[7]*v7;
                a0 += ar[base]       * vl;
                a1 += ar[base + 64]  * vl;
                a2 += ar[base + 128] * vl;
                a3 += ar[base + 192] * vl;
                a4 += ar[base + 256] * vl;
            }
        } else {
            #pragma unroll 2
            for (int ec = 0; ec < nn; ec++) {
                const float* ar = g_Aemb + (size_t)se[ec] * FV;
                const float* rp = &Re[ec * 8];
                float vl = rp[0]*v0 + rp[1]*v1 + rp[2]*v2 + rp[3]*v3
                         + rp[4]*v4 + rp[5]*v5 + rp[6]*v6 + rp[7]*v7;
                a0 += ar[base]       * vl;
                a1 += ar[base + 32]  * vl;
                a2 += ar[base + 64]  * vl;
                a3 += ar[base + 96]  * vl;
                a4 += ar[base + 128] * vl;
                a5 += ar[base + 160] * vl;
                a6 += ar[base + 192] * vl;
            }
        }
        __syncthreads();
    }

    // scatter accumulators into Bsh (each thread owns columns base + m*Kl_m)
    if (lvl == 0) {
        Bsh[base] = 0.1f * a0;
    } else if (lvl == 1) {
        Bsh[base] = 0.1f * a0; Bsh[base + 96] = 0.1f * a1; Bsh[base + 192] = 0.1f * a2;
    } else if (lvl == 2) {
        Bsh[base] = 0.1f * a0; Bsh[base + 64] = 0.1f * a1; Bsh[base + 128] = 0.1f * a2;
        Bsh[base + 192] = 0.1f * a3; Bsh[base + 256] = 0.1f * a4;
    } else {
        Bsh[base] = 0.1f * a0; Bsh[base + 32] = 0.1f * a1; Bsh[base + 64] = 0.1f * a2;
        Bsh[base + 96] = 0.1f * a3; Bsh[base + 128] = 0.1f * a4;
        Bsh[base + 160] = 0.1f * a5; Bsh[base + 192] = 0.1f * a6;
    }
    __syncthreads();

    // invariants (192): l1 96, l2 64, l3 32
    if (t < 192) {
        int off, KK, cnt, kk;
        float norm;
        if (t < 96)       { off = 128; KK = 96; cnt = 3; kk = t;       norm = 0.5773502691896258f; }
        else if (t < 160) { off = 416; KK = 64; cnt = 5; kk = t - 96;  norm = 0.4472135954999579f; }
        else              { off = 736; KK = 32; cnt = 7; kk = t - 160; norm = 0.3779644730092272f; }
        float s = 0.f;
        for (int m = 0; m < cnt; m++) { float v = Bsh[off + m * KK + kk]; s += v * v; }
        invsh[t] = s * norm;
    }
    __syncthreads();

    g_fpre[(size_t)i * FP + t] = (t < 128) ? Bsh[t] : invsh[t - 128];
}

// ---------------- kernel 6: tail (inv@N + MLP), 16 atoms / block -------------
__global__ void __launch_bounds__(256) k_tail(
    const float* __restrict__ N1, const float* __restrict__ N2,
    const float* __restrict__ N3,
    const float* __restrict__ W1, const float* __restrict__ W2,
    const float* __restrict__ w_out, const float* __restrict__ comp,
    const int* __restrict__ species) {
    __shared__ float fin[16 * FP];     // 20 KB
    __shared__ float f2sh[16 * 128];   // 8 KB (reused for stage-3 partials)
    __shared__ float h1sh[16 * 128];   // 8 KB

    int t = threadIdx.x;
    int blk = blockIdx.x;
    int c = t & 127;
    int g = t >> 7;            // 0/1: atom half
    int abase = g * 8;

    for (int j = t; j < 16 * FP; j += 256)
        fin[j] = g_fpre[(size_t)blk * 16 * FP + j];
    __syncthreads();

    // stage 1: f2 = B0 + inv @ Ncat
    float acc[8];
    #pragma unroll
    for (int a = 0; a < 8; a++) acc[a] = fin[(abase + a) * FP + c];
    for (int j = 0; j < 96; j++) {
        float nv = N1[j * 128 + c];
        #pragma unroll
        for (int a = 0; a < 8; a++) acc[a] += fin[(abase + a) * FP + 128 + j] * nv;
    }
    for (int j = 0; j < 64; j++) {
        float nv = N2[j * 128 + c];
        #pragma unroll
        for (int a = 0; a < 8; a++) acc[a] += fin[(abase + a) * FP + 224 + j] * nv;
    }
    for (int j = 0; j < 32; j++) {
        float nv = N3[j * 128 + c];
        #pragma unroll
        for (int a = 0; a < 8; a++) acc[a] += fin[(abase + a) * FP + 288 + j] * nv;
    }
    #pragma unroll
    for (int a = 0; a < 8; a++) f2sh[(abase + a) * 128 + c] = acc[a];
    __syncthreads();

    // stage 2: h1 = silu(f2 @ W1)
    float acc2[8];
    #pragma unroll
    for (int a = 0; a < 8; a++) acc2[a] = 0.f;
    for (int kk = 0; kk < 128; kk++) {
        float w = W1[kk * 128 + c];
        #pragma unroll
        for (int a = 0; a < 8; a++) acc2[a] += f2sh[(abase + a) * 128 + kk] * w;
    }
    #pragma unroll
    for (int a = 0; a < 8; a++) {
        float s = acc2[a];
        h1sh[(abase + a) * 128 + c] = s / (1.0f + expf(-s));
    }
    __syncthreads();

    // stage 3: h2 = h1 @ W2 ; partial = h2 * w_out
    float acc3[8];
    #pragma unroll
    for (int a = 0; a < 8; a++) acc3[a] = 0.f;
    for (int kk = 0; kk < 128; kk++) {
        float w = W2[kk * 128 + c];
        #pragma unroll
        for (int a = 0; a < 8; a++) acc3[a] += h1sh[(abase + a) * 128 + kk] * w;
    }
    float wo = w_out[c];
    __syncthreads();   // f2sh reuse
    #pragma unroll
    for (int a = 0; a < 8; a++) f2sh[(abase + a) * 128 + c] = acc3[a] * wo;
    __syncthreads();

    if (t < 16) {
        float s = 0.f;
        for (int j = 0; j < 128; j++) s += f2sh[t * 128 + j];
        int idx = blk * 16 + t;
        g_eatom[idx] = s + comp[species[idx]];
    }
}

// ---------------- kernel 7: deterministic final reduction --------------------
__global__ void k_reduce(float* __restrict__ out) {
    __shared__ double sh[1024];
    int t = threadIdx.x;
    double s = 0.0;
    for (int i = t; i < N_ATOMS; i += 1024) s += (double)g_eatom[i];
    sh[t] = s;
    __syncthreads();
    for (int o = 512; o > 0; o >>= 1) {
        if (t < o) sh[t] += sh[t + o];
        __syncthreads();
    }
    if (t == 0) out[0] = (float)sh[0];
}

// ---------------- launch ------------------------------------------------------
extern "C" void kernel_launch(void* const* d_in, const int* in_sizes, int n_in,
                              void* d_out, int out_size) {
    const float *pos = 0, *emb = 0, *Wr0 = 0, *Wr1 = 0, *Wr2 = 0, *Wr3 = 0;
    const float *Vr0 = 0, *Vr1 = 0, *Vr2 = 0, *Vr3 = 0;
    const float *N1 = 0, *N2 = 0, *N3 = 0, *W1 = 0, *W2 = 0, *w_out = 0, *comp = 0;
    const int *species = 0, *snd = 0, *rcv = 0;

    for (int i = 0; i < n_in; i++) {
        int s = in_sizes[i];
        const void* p = d_in[i];
        switch (s) {
            case 30000:  pos = (const float*)p; break;
            case 64:     emb = (const float*)p; break;
            case 10000:  species = (const int*)p; break;
            case 320000: if (!snd) snd = (const int*)p; else rcv = (const int*)p; break;
            case 1024:   if (!Wr0) Wr0 = (const float*)p; else Vr0 = (const float*)p; break;
            case 768:    if (!Wr1) Wr1 = (const float*)p; else Vr1 = (const float*)p; break;
            case 512:    if (!Wr2) Wr2 = (const float*)p; else Vr2 = (const float*)p; break;
            case 256:    if (!Wr3) Wr3 = (const float*)p; else Vr3 = (const float*)p; break;
            case 12288:  N1 = (const float*)p; break;  // M1 then N1: keep LAST
            case 8192:   N2 = (const float*)p; break;  // M2 then N2: keep LAST
            case 4096:   N3 = (const float*)p; break;  // M3 then N3: keep LAST
            case 16384:  if (!W1) W1 = (const float*)p; else W2 = (const float*)p; break;
            case 128:    w_out = (const float*)p; break;
            case 4:      comp = (const float*)p; break;
            default: break;
        }
    }

    float* out = (float*)d_out;

    k_zero<<<(N_ATOMS + 255) / 256, 256>>>();
    k_geom<<<(N_EDGES + 255) / 256, 256>>>(pos, species, snd, rcv);
    k_scan<<<1, 1024>>>();
    k_fill<<<(N_EDGES + 255) / 256, 256>>>(rcv);
    k_phaseA<<<N_ATOMS, 128>>>(emb, Wr0, Wr1, Wr2, Wr3, species);
    k_phaseB<<<N_ATOMS, 320>>>(Vr0, Vr1, Vr2, Vr3, snd);
    k_tail<<<N_ATOMS / 16, 256>>>(N1, N2, N3, W1, W2, w_out, comp, species);
    k_reduce<<<1, 1024>>>(out);
}